// round 16
// baseline (speedup 1.0000x reference)
#include <cuda_runtime.h>
#include <math.h>

#define HID   1024
#define SEQ   4096
#define G3    3072            // 3*HID
#define GIROWS 4098           // SEQ tokens + SOS row + EOS row
#define NBLK  128             // persistent CTAs (each handles BOTH dirs)
#define UPB   8               // hidden units per block (NBLK*UPB == HID)
#define RPB   24              // w_hh rows per block (3*UPB)

// ---------------- scratch (static device allocations only) ----------------
__device__ float g_GI[(size_t)GIROWS * G3];   // precomputed input gates (+b_ih)
__device__ float g_h[2][2][HID];              // [dir][step parity][unit]
__device__ unsigned int g_bar[2][SEQ + 1];    // per-direction per-step counters
__device__ int   g_tok64;                     // 1 if tokens are int64

// ---------------- packed f32x2 helpers (sm_103a FFMA2 via PTX) ----------------
__device__ __forceinline__ unsigned long long ffma2(
    unsigned long long a, unsigned long long b, unsigned long long c)
{
    unsigned long long d;
    asm("fma.rn.f32x2 %0, %1, %2, %3;" : "=l"(d) : "l"(a), "l"(b), "l"(c));
    return d;
}
__device__ __forceinline__ float hsum_f32x2(unsigned long long p) {
    unsigned int lo, hi;
    asm("mov.b64 {%0, %1}, %2;" : "=r"(lo), "=r"(hi) : "l"(p));
    return __uint_as_float(lo) + __uint_as_float(hi);
}
__device__ __forceinline__ unsigned long long pack2(float x, float y) {
    unsigned long long p;
    asm("mov.b64 %0, {%1, %2};" : "=l"(p) : "r"(__float_as_uint(x)), "r"(__float_as_uint(y)));
    return p;
}

// ---------------- acq/rel barrier primitives (proven in R11) ----------------
__device__ __forceinline__ void bar_arrive_release(unsigned int* p) {
    asm volatile("red.release.gpu.global.add.u32 [%0], %1;"
                 :: "l"(p), "r"(1u) : "memory");
}
__device__ __forceinline__ unsigned int ld_acquire_gpu(const unsigned int* p) {
    unsigned int v;
    asm volatile("ld.acquire.gpu.global.u32 %0, [%1];"
                 : "=r"(v) : "l"(p) : "memory");
    return v;
}

// Zero per-step barrier counters (every launch) + detect token dtype.
// int64 little-endian with values < 2^31 has all-zero high words; int32 data
// has random tokens there. P(misdetect) ~ (1/50257)^64.
__global__ void setup_kernel(const int* toks_i32) {
    int i = blockIdx.x * blockDim.x + threadIdx.x;
    unsigned int* b = &g_bar[0][0];
    for (; i < 2 * (SEQ + 1); i += gridDim.x * blockDim.x) b[i] = 0u;
    if (blockIdx.x == 0 && threadIdx.x == 0) {
        int is64 = 1;
        for (int k = 0; k < 64; k++) {
            if (toks_i32[2 * k + 1] != 0 || toks_i32[2 * k] < 0) { is64 = 0; break; }
        }
        g_tok64 = is64;
    }
}

// ---------------- GI GEMM: GI[m][n] = b_ih[n] + emb[tok(m)] . w_ih[n] ----------------
__global__ __launch_bounds__(256) void gi_gemm_kernel(
    const void* __restrict__ toks_raw,
    const float* __restrict__ emb,
    const float* __restrict__ w_ih,
    const float* __restrict__ b_ih,
    int vocab)
{
    __shared__ float As[16][64];
    __shared__ float Bs[16][64];

    const int tx = threadIdx.x;       // 0..15
    const int ty = threadIdx.y;       // 0..15
    const int tid = ty * 16 + tx;
    const int m0 = blockIdx.y * 64;
    const int n0 = blockIdx.x * 64;

    const int lr = tid >> 2;          // 0..63 row within tile
    const int lk = (tid & 3) << 2;    // 0,4,8,12 k-offset

    const int am = m0 + lr;
    long long tok = 0;                // SOS row default
    if (am < SEQ) {
        if (g_tok64) tok = ((const long long*)toks_raw)[am];
        else         tok = (long long)((const int*)toks_raw)[am];
    }
    else if (am == SEQ)     tok = 0;  // SOS
    else if (am == SEQ + 1) tok = 1;  // EOS
    if (tok < 0) tok = 0;
    if (tok >= vocab) tok = vocab - 1;

    const float* Arow = emb + (size_t)tok * HID;
    const float* Brow = w_ih + (size_t)(n0 + lr) * HID;

    unsigned long long c2[4][2];
    #pragma unroll
    for (int i = 0; i < 4; i++) { c2[i][0] = 0ull; c2[i][1] = 0ull; }

    for (int k0 = 0; k0 < HID; k0 += 16) {
        float4 a = *(const float4*)(Arow + k0 + lk);
        float4 b = *(const float4*)(Brow + k0 + lk);
        As[lk + 0][lr] = a.x; As[lk + 1][lr] = a.y;
        As[lk + 2][lr] = a.z; As[lk + 3][lr] = a.w;
        Bs[lk + 0][lr] = b.x; Bs[lk + 1][lr] = b.y;
        Bs[lk + 2][lr] = b.z; Bs[lk + 3][lr] = b.w;
        __syncthreads();
        #pragma unroll
        for (int kk = 0; kk < 16; kk++) {
            float4 av = *(const float4*)&As[kk][ty << 2];
            float4 bv = *(const float4*)&Bs[kk][tx << 2];
            ulonglong2 b2 = *(ulonglong2*)&bv;
            float ar[4] = {av.x, av.y, av.z, av.w};
            #pragma unroll
            for (int i = 0; i < 4; i++) {
                unsigned long long aa = pack2(ar[i], ar[i]);
                c2[i][0] = ffma2(aa, b2.x, c2[i][0]);
                c2[i][1] = ffma2(aa, b2.y, c2[i][1]);
            }
        }
        __syncthreads();
    }

    #pragma unroll
    for (int i = 0; i < 4; i++) {
        int m = m0 + (ty << 2) + i;
        if (m < GIROWS) {
            float cv[4];
            unsigned int lo, hi;
            asm("mov.b64 {%0,%1}, %2;" : "=r"(lo), "=r"(hi) : "l"(c2[i][0]));
            cv[0] = __uint_as_float(lo); cv[1] = __uint_as_float(hi);
            asm("mov.b64 {%0,%1}, %2;" : "=r"(lo), "=r"(hi) : "l"(c2[i][1]));
            cv[2] = __uint_as_float(lo); cv[3] = __uint_as_float(hi);
            #pragma unroll
            for (int jj = 0; jj < 4; jj++) {
                int n = n0 + (tx << 2) + jj;
                g_GI[(size_t)m * G3 + n] = cv[jj] + b_ih[n];
            }
        }
    }
}

// ---------------- persistent recurrence, direction-pipelined barriers ----------
// 128 co-resident CTAs (cooperative launch for residency only). Per step, the
// fwd phase [wait fwd(t-1) -> dots -> gate -> publish fwd(t)] is followed by
// the bwd phase; each direction's barrier fill-to-detect interval is bridged
// by the other direction's compute, so waits degenerate to a fast-path poll.
// Barrier = R11's proven elected-poller: __syncthreads -> tid0 red.release /
// spin ld.acquire -> __syncthreads. Parity double-buffer per direction.
__global__ __launch_bounds__(256, 1) void gru_rec_kernel(
    const float* __restrict__ w_hh,
    const float* __restrict__ b_hh,
    float* __restrict__ out)
{
    __shared__ __align__(16) float sh_h[2][HID];
    __shared__ float sh_part[4][RPB];   // [wkg][row], reused per phase

    const int tid  = threadIdx.x;
    const int lane = tid & 31;
    const int warp = tid >> 5;
    const int j0   = blockIdx.x * UPB;

    const int wkg  = warp & 3;        // K group: [256*wkg, 256*wkg+256)
    const int wrg  = warp >> 2;       // row group: [12*wrg, 12*wrg+12)
    const int ksub = lane & 7;        // K sub-offset within group
    const int rsub = lane >> 3;       // row within group-of-4

    // Register-cache weights: w4[p][i] = w_hh[row_p][256*wkg + 4*ksub + 32*i],
    // row_p = 12*wrg + 4*p + rsub, mapped to gate*HID + unit.
    float4 w4[3][8];
    #pragma unroll
    for (int p = 0; p < 3; p++) {
        int rr = 12 * wrg + 4 * p + rsub;              // 0..23
        int grow = (rr >> 3) * HID + j0 + (rr & 7);    // gate*HID + unit
        const float* wp = w_hh + (size_t)grow * HID + 256 * wkg + 4 * ksub;
        #pragma unroll
        for (int i = 0; i < 8; i++)
            w4[p][i] = *(const float4*)(wp + 32 * i);
    }

    // Gating-thread constants (tid < 8): one hidden unit, both directions.
    const int u = tid;                 // unit within block (valid when tid<8)
    const int j = j0 + (tid & 7);
    float bhr = 0.f, bhz = 0.f, bhn = 0.f;
    if (tid < UPB) {
        bhr = __ldg(b_hh + j);
        bhz = __ldg(b_hh + HID + j);
        bhn = __ldg(b_hh + 2 * HID + j);
    }

    float* outHid = out + HID;   // hiddens start after h_b

    for (int step = 0; step <= SEQ; step++) {
        // ---- GI prefetch for both dirs (step-dependent only) ----
        float irf = 0.f, izf = 0.f, innf = 0.f;
        float irb = 0.f, izb = 0.f, innb = 0.f;
        if (tid < UPB) {
            int rowf = (step == 0) ? SEQ     : step - 1;
            int rowb = (step == 0) ? SEQ + 1 : SEQ - step;
            const float* gf = g_GI + (size_t)rowf * G3;
            const float* gb = g_GI + (size_t)rowb * G3;
            irf  = __ldcg(gf + j);  izf = __ldcg(gf + HID + j);  innf = __ldcg(gf + 2 * HID + j);
            irb  = __ldcg(gb + j);  izb = __ldcg(gb + HID + j);  innb = __ldcg(gb + 2 * HID + j);
        }

        float hnF = 0.f, hnB = 0.f;

        #pragma unroll
        for (int d = 0; d < 2; d++) {
            // ---- acquire previous h for this dir (fast-path poll) ----
            if (step > 0) {
                if (tid == 0) {
                    while (ld_acquire_gpu(&g_bar[d][step - 1]) < NBLK) { }
                }
                __syncthreads();
                const int p = (step - 1) & 1;
                ((float4*)sh_h[d])[tid] = __ldcg((const float4*)g_h[d][p] + tid);
            } else {
                ((float4*)sh_h[d])[tid] = make_float4(0.f, 0.f, 0.f, 0.f);
            }
            __syncthreads();

            // ---- stage this lane's h slice into registers ----
            ulonglong2 hr[8];
            {
                const ulonglong2* sh = (const ulonglong2*)sh_h[d];
                #pragma unroll
                for (int i = 0; i < 8; i++)
                    hr[i] = sh[64 * wkg + ksub + 8 * i];
            }

            // ---- all-register packed dots: 3 row-passes x 8 K-iters ----
            float acc[3];
            #pragma unroll
            for (int p = 0; p < 3; p++) {
                unsigned long long a2 = 0ull;
                #pragma unroll
                for (int i = 0; i < 8; i++) {
                    const ulonglong2 wv = *(const ulonglong2*)&w4[p][i];
                    a2 = ffma2(wv.x, hr[i].x, a2);
                    a2 = ffma2(wv.y, hr[i].y, a2);
                }
                acc[p] = hsum_f32x2(a2);
            }
            #pragma unroll
            for (int off = 4; off; off >>= 1) {
                #pragma unroll
                for (int p = 0; p < 3; p++)
                    acc[p] += __shfl_xor_sync(0xffffffffu, acc[p], off);
            }
            if (ksub == 0) {
                #pragma unroll
                for (int p = 0; p < 3; p++) {
                    int rr = 12 * wrg + 4 * p + rsub;
                    sh_part[wkg][rr] = acc[p];
                }
            }
            __syncthreads();

            // ---- gating (tid < 8): compute + publish this dir's h ----
            if (tid < UPB) {
                float ghr = bhr, ghz = bhz, ghn = bhn;
                #pragma unroll
                for (int kg = 0; kg < 4; kg++) {
                    ghr += sh_part[kg][u];
                    ghz += sh_part[kg][8 + u];
                    ghn += sh_part[kg][16 + u];
                }
                float ir = d ? irb : irf, iz = d ? izb : izf, inn = d ? innb : innf;
                float rg = __fdividef(1.f, 1.f + __expf(-(ir + ghr)));
                float zg = __fdividef(1.f, 1.f + __expf(-(iz + ghz)));
                float y  = inn + rg * ghn;
                y = fminf(fmaxf(y, -15.f), 15.f);
                float e2 = __expf(-2.f * y);
                float ng = __fdividef(1.f - e2, 1.f + e2);
                float hp = sh_h[d][j];
                float hn = (1.f - zg) * ng + zg * hp;
                if (d) hnB = hn; else hnF = hn;
                __stcg(&g_h[d][step & 1][j], hn);
            }

            // ---- release this dir's step (stores ordered by syncthreads) ----
            __syncthreads();
            if (tid == 0) bar_arrive_release(&g_bar[d][step]);
        }

        // ---- output stores, off the critical path ----
        if (tid < UPB && step > 0) {
            int tF = step - 1;
            int tB = SEQ - step;
            outHid[(size_t)tF * (2 * HID) + j]       = hnF;   // fwd hidden
            outHid[(size_t)tB * (2 * HID) + HID + j] = hnB;   // bwd hidden
            if (tB == 0) out[j] = hnB;                        // h_b
        }
    }
}

// ---------------- launch ----------------
extern "C" void kernel_launch(void* const* d_in, const int* in_sizes, int n_in,
                              void* d_out, int out_size)
{
    const void*  toks = d_in[0];
    const float* emb  = (const float*)d_in[1];
    const float* w_ih = (const float*)d_in[2];
    const float* w_hh = (const float*)d_in[3];
    const float* b_ih = (const float*)d_in[4];
    const float* b_hh = (const float*)d_in[5];
    float*       out  = (float*)d_out;

    int vocab = in_sizes[1] / HID;   // emb rows

    setup_kernel<<<16, 256>>>((const int*)toks);
    gi_gemm_kernel<<<dim3(G3 / 64, (GIROWS + 63) / 64), dim3(16, 16)>>>(toks, emb, w_ih, b_ih, vocab);

    // Cooperative launch: guarantees all 128 CTAs co-resident (spin safety).
    cudaLaunchConfig_t cfg = {};
    cfg.gridDim = dim3(NBLK, 1, 1);
    cfg.blockDim = dim3(256, 1, 1);
    cfg.dynamicSmemBytes = 0;
    cfg.stream = 0;
    cudaLaunchAttribute attr[1];
    attr[0].id = cudaLaunchAttributeCooperative;
    attr[0].val.cooperative = 1;
    cfg.attrs = attr;
    cfg.numAttrs = 1;
    cudaLaunchKernelEx(&cfg, gru_rec_kernel, w_hh, b_hh, out);
}